// round 15
// baseline (speedup 1.0000x reference)
#include <cuda_runtime.h>
#include <cuda_fp16.h>
#include <stdint.h>

// ============================================================================
// Problem constants (fixed per reference source)
// ============================================================================
#define K_DIM 4096
#define N_DIM 4096
#define M_MAX 8192
#define HASH_MASK 0xFFFFF        // HASH_SIZE = 2^20
#define P_CONST 56598313LL       // RzLinear.P (prime), hardcoded in reference

// Scratch (device globals; no allocation allowed)
// g_A: fragment-major fp16, [M/16][K/16][32 lanes][4 b32 words]; entry
//      (mt,k16,lane={lq*4+lr}) = m16n8k16 A-fragment.
// g_B: pair-major fp16, uint2 index r*N+n with r = k16*4 + lr:
//      .x = half2(w[k0,n], w[k0+1,n]), .y = half2(w[k0+8,n], w[k0+9,n]),
//      k0 = k16*16 + 2*lr.
__device__ uint32_t g_A[(size_t)M_MAX * K_DIM / 2];
__device__ uint32_t g_B[(size_t)K_DIM * N_DIM / 2];
__device__ int      g_rowmod[K_DIM];              // (k*r3 + r1) % P
__device__ int      g_colmod[N_DIM];              // (n*r2) % P

__device__ __forceinline__ uint32_t pack_h2(float lo, float hi) {
    __half2 h = __floats2half2_rn(lo, hi);
    return *(uint32_t*)&h;
}
__device__ __forceinline__ uint32_t smem_u32(const void* p) {
    uint32_t a;
    asm("{ .reg .u64 t; cvta.to.shared.u64 t, %1; cvt.u32.u64 %0, t; }"
        : "=r"(a) : "l"(p));
    return a;
}
__device__ __forceinline__ void cp_async16(uint32_t dst, const void* src) {
    asm volatile("cp.async.cg.shared.global [%0], [%1], 16;"
                 :: "r"(dst), "l"(src) : "memory");
}
#define CP_COMMIT() asm volatile("cp.async.commit_group;" ::: "memory")
#define CP_WAIT1()  asm volatile("cp.async.wait_group 1;"  ::: "memory")
#define CP_WAIT0()  asm volatile("cp.async.wait_group 0;"  ::: "memory")

// m16n8k16 fp16 MMA, f32 accumulate (generic PTX, sm_80+)
__device__ __forceinline__ void mma_f16(float c[4], uint32_t a0, uint32_t a1,
                                        uint32_t a2, uint32_t a3,
                                        uint32_t b0, uint32_t b1) {
    asm volatile(
        "mma.sync.aligned.m16n8k16.row.col.f32.f16.f16.f32 "
        "{%0,%1,%2,%3}, {%4,%5,%6,%7}, {%8,%9}, {%0,%1,%2,%3};"
        : "+f"(c[0]), "+f"(c[1]), "+f"(c[2]), "+f"(c[3])
        : "r"(a0), "r"(a1), "r"(a2), "r"(a3), "r"(b0), "r"(b1));
}

// ============================================================================
// Kernel 1: hash residue tables (self-detects int64 vs int32 materialization)
// ============================================================================
__global__ void hash_tables_kernel(const void* __restrict__ rn_raw) {
    const long long* rn64 = (const long long*)rn_raw;
    const int*       rn32 = (const int*)rn_raw;
    long long r1, r2, r3;
    if (rn64[0] == P_CONST) { r1 = rn64[1]; r2 = rn64[2]; r3 = rn64[3]; }
    else                    { r1 = rn32[1]; r2 = rn32[2]; r3 = rn32[3]; }
    int i = blockIdx.x * blockDim.x + threadIdx.x;
    if (i < K_DIM) g_rowmod[i] = (int)(((long long)i * r3 + r1) % P_CONST);
    if (i < N_DIM) g_colmod[i] = (int)(((long long)i * r2) % P_CONST);
}

// ============================================================================
// Kernel 2 (fused prep): even blocks convert x -> fp16 fragment-major A;
// odd blocks gather W -> pair-major fp16 B (different bottlenecks overlap).
// ============================================================================
__global__ void prep_kernel(const float* __restrict__ x,
                            const float* __restrict__ hw,
                            int a_total, int g_total) {
    const int half_id = blockIdx.x >> 1;
    if ((blockIdx.x & 1) == 0) {
        // ---- cvt_a: fragment-major permutation ----
        int t = half_id * blockDim.x + threadIdx.x;
        if (t >= a_total) return;
        const int lane = t & 31;
        const int k16  = (t >> 5) & (K_DIM / 16 - 1);
        const int mt   = t >> (5 + 8);            // K/16 = 256 -> 8 bits
        const int lq = lane >> 2, lr = lane & 3;
        const float* xm = x + (size_t)(mt * 16) * K_DIM + k16 * 16;
        const float2 p0 = *(const float2*)(xm + (size_t)lq * K_DIM + 2 * lr);
        const float2 p1 = *(const float2*)(xm + (size_t)(lq + 8) * K_DIM + 2 * lr);
        const float2 p2 = *(const float2*)(xm + (size_t)lq * K_DIM + 2 * lr + 8);
        const float2 p3 = *(const float2*)(xm + (size_t)(lq + 8) * K_DIM + 2 * lr + 8);
        uint4 o;
        o.x = pack_h2(p0.x, p0.y);
        o.y = pack_h2(p1.x, p1.y);
        o.z = pack_h2(p2.x, p2.y);
        o.w = pack_h2(p3.x, p3.y);
        ((uint4*)g_A)[t] = o;
    } else {
        // ---- gather: W -> pair-major fp16 ----
        const int P = (int)P_CONST;
        int t = half_id * blockDim.x + threadIdx.x;
        if (t >= g_total) return;
        const int n  = t & (N_DIM - 1);
        const int r  = t >> 12;                     // k16*4 + lr
        const int lr = r & 3;
        const int k0 = (r >> 2) * 16 + 2 * lr;

        const int rm0 = g_rowmod[k0];
        const int rm1 = g_rowmod[k0 + 1];
        const int rm2 = g_rowmod[k0 + 8];
        const int rm3 = g_rowmod[k0 + 9];
        const int c   = g_colmod[n];

        int s0 = rm0 + c; if (s0 >= P) s0 -= P;
        int s1 = rm1 + c; if (s1 >= P) s1 -= P;
        int s2 = rm2 + c; if (s2 >= P) s2 -= P;
        int s3 = rm3 + c; if (s3 >= P) s3 -= P;

        const float w0 = __ldg(hw + (s0 & HASH_MASK));
        const float w1 = __ldg(hw + (s1 & HASH_MASK));
        const float w2 = __ldg(hw + (s2 & HASH_MASK));
        const float w3 = __ldg(hw + (s3 & HASH_MASK));

        uint2 o;
        o.x = pack_h2(w0, w1);
        o.y = pack_h2(w2, w3);
        ((uint2*)g_B)[t] = o;
    }
}

// ============================================================================
// Kernel 3: fp16 tensor-core GEMM via mma.sync m16n8k16
//   CTA tile 128x128, STAGE = 64 k (4 k16-steps), 256 thr (8 warps 2x4 ->
//   warp tile 64x32), 3-stage cp.async pipeline, ONE barrier per 64 k,
//   2 CTAs per SM (barrier decoupling across independent CTAs).
//   NEW: stage-prefetch cp.async for kt+2 is issued IMMEDIATELY after the
//   barrier (before the MMA burst) — safe because the written slot
//   (kt+2)%3 = (kt-1)%3 was last read in iter kt-1, before this barrier —
//   giving the async group a full extra compute burst to land and letting
//   STS wavefronts interleave with fragment LDS instead of bunching.
//   A fragments: 1x LDS.128 (fragment-major, conflict-free).
//   B fragments: 1x LDS.64 (pair-major, SB_W=264 ≡ 8 mod 32 words).
// ============================================================================
#define SB_W 264
#define A_STAGE_B (8 * 4 * 32 * 16)                // 16384 (8 mtiles x 4 ks)
#define B_STAGE_B (16 * SB_W * 4)                  // 16896 (16 rows)
#define STAGE_B   (A_STAGE_B + B_STAGE_B)          // 33280
#define NSTAGE 3
#define SMEM_GEMM (NSTAGE * STAGE_B)               // 99840 (x2 CTAs = 199680)
#define NK64      (K_DIM / 64)                     // 64 stages of work

__device__ __forceinline__ void load_stage(uint32_t sbase, int stage,
                                           int m0, int n0, int kt, int tid) {
    const uint32_t a_s = sbase + stage * STAGE_B;
    const uint32_t b_s = a_s + A_STAGE_B;
    // A: 32 fragment-chunks of 512B (i = mtile 0..7, j = ks 0..3);
    //    1024 x 16B transfers, 4 per thread; gmem chunk contiguous.
    #pragma unroll
    for (int p = 0; p < 4; p++) {
        const int u     = tid + p * 256;
        const int chunk = u >> 5;            // 0..31
        const int lane  = u & 31;
        const int i = chunk >> 2;            // mtile within CTA
        const int j = chunk & 3;             // ks
        const uint32_t* src = g_A +
            (((size_t)(m0 / 16 + i) * (K_DIM / 16) + (kt * 4 + j)) * 32
             + lane) * 4;
        cp_async16(a_s + u * 16, src);
    }
    // B: 16 rows x 256 words (64 x 16B chunks per row); 4 per thread.
    #pragma unroll
    for (int p = 0; p < 4; p++) {
        const int u = tid + p * 256;
        const int r = u >> 6;                // 0..15
        const int c = u & 63;
        const uint32_t* src =
            g_B + ((size_t)(kt * 16 + r) * N_DIM + n0) * 2 + c * 4;
        cp_async16(b_s + r * (SB_W * 4) + c * 16, src);
    }
}

__global__ __launch_bounds__(256, 2)
void gemm_mma_kernel(const float* __restrict__ bias, float* __restrict__ C) {
    extern __shared__ char smem[];
    const uint32_t sbase = smem_u32(smem);
    const int tid  = threadIdx.x;
    const int wid  = tid >> 5;
    const int lane = tid & 31;
    const int lq = lane >> 2;     // 0..7
    const int lr = lane & 3;      // 0..3
    const int wm = wid & 1;       // 2 m-halves of 64
    const int wn = wid >> 1;      // 4 n-slices of 32

    const int m_blk = blockIdx.y * 128;
    const int n_blk = blockIdx.x * 128;

    float acc[4][4][4];
    #pragma unroll
    for (int i = 0; i < 4; i++)
        #pragma unroll
        for (int j = 0; j < 4; j++)
            #pragma unroll
            for (int r = 0; r < 4; r++) acc[i][j][r] = 0.0f;

    load_stage(sbase, 0, m_blk, n_blk, 0, tid); CP_COMMIT();
    load_stage(sbase, 1, m_blk, n_blk, 1, tid); CP_COMMIT();

    int st = 0;
    for (int kt = 0; kt < NK64; kt++) {
        CP_WAIT1();
        __syncthreads();    // single barrier per 64 k

        // Prefetch kt+2 FIRST: slot (st+2)%3 = (kt-1)%3 was last read in
        // iter kt-1, whose readers all passed the barrier above.
        if (kt + 2 < NK64) {
            int ws = st + 2; if (ws >= NSTAGE) ws -= NSTAGE;
            load_stage(sbase, ws, m_blk, n_blk, kt + 2, tid);
        }
        CP_COMMIT();   // keep group count in lockstep even when empty

        const uint32_t* As = (const uint32_t*)(smem + st * STAGE_B);
        const uint32_t* Bs = (const uint32_t*)(smem + st * STAGE_B + A_STAGE_B);

        const uint32_t* a_base = As + (wm * 16) * 128 + lane * 4;
        const uint32_t* b_base = Bs + (wn * 32 + lq) * 2;

        #pragma unroll
        for (int ks = 0; ks < 4; ks++) {
            uint4 a[4];
            #pragma unroll
            for (int im = 0; im < 4; im++)
                a[im] = *(const uint4*)(a_base + (im * 4 + ks) * 128);
            uint2 b[4];
            #pragma unroll
            for (int jn = 0; jn < 4; jn++)
                b[jn] = *(const uint2*)
                    (b_base + (ks * 4 + lr) * SB_W + jn * 16);
            #pragma unroll
            for (int im = 0; im < 4; im++)
                #pragma unroll
                for (int jn = 0; jn < 4; jn++)
                    mma_f16(acc[im][jn], a[im].x, a[im].y, a[im].z, a[im].w,
                            b[jn].x, b[jn].y);
        }

        st = (st == NSTAGE - 1) ? 0 : st + 1;
    }
    CP_WAIT0();

    // epilogue: bias + direct stores
    #pragma unroll
    for (int jn = 0; jn < 4; jn++) {
        const int c0 = n_blk + wn * 32 + jn * 8 + 2 * lr;
        const float bx = __ldg(bias + c0);
        const float by = __ldg(bias + c0 + 1);
        #pragma unroll
        for (int im = 0; im < 4; im++) {
            const int r0 = m_blk + wm * 64 + im * 16 + lq;
            float2 v0, v1;
            v0.x = acc[im][jn][0] + bx; v0.y = acc[im][jn][1] + by;
            v1.x = acc[im][jn][2] + bx; v1.y = acc[im][jn][3] + by;
            *(float2*)(C + (size_t)r0 * N_DIM + c0)       = v0;
            *(float2*)(C + (size_t)(r0 + 8) * N_DIM + c0) = v1;
        }
    }
}

// ============================================================================
// Host launch. Inputs routed by element count (immune to metadata ordering):
//   <=8 elems -> random_numbers; 2^20 -> hashed_weight; 4096 -> bias;
//   largest -> x. Output f32 [M, N_DIM].
// ============================================================================
extern "C" void kernel_launch(void* const* d_in, const int* in_sizes, int n_in,
                              void* d_out, int out_size) {
    const float* x = nullptr; const float* hw = nullptr;
    const void* rn = nullptr; const float* bias = nullptr;
    long long max_sz = -1; int max_i = 0;
    for (int i = 0; i < n_in; i++)
        if ((long long)in_sizes[i] > max_sz) { max_sz = in_sizes[i]; max_i = i; }
    x = (const float*)d_in[max_i];
    for (int i = 0; i < n_in; i++) {
        if (i == max_i) continue;
        if (in_sizes[i] <= 8)              rn   = d_in[i];
        else if (in_sizes[i] == (1 << 20)) hw   = (const float*)d_in[i];
        else if (in_sizes[i] == N_DIM)     bias = (const float*)d_in[i];
    }
    float* out = (float*)d_out;
    const int M = (int)(max_sz / K_DIM);   // 8192

    hash_tables_kernel<<<(K_DIM + 255) / 256, 256>>>(rn);

    const int a_total = (M / 16) * (K_DIM / 16) * 32;
    const int g_total = (K_DIM / 4) * N_DIM;
    const int a_blocks = (a_total + 255) / 256;
    const int g_blocks = (g_total + 255) / 256;
    const int mx_blocks = (a_blocks > g_blocks ? a_blocks : g_blocks);
    prep_kernel<<<2 * mx_blocks, 256>>>(x, hw, a_total, g_total);

    static bool smem_set = false;
    if (!smem_set) {
        cudaFuncSetAttribute(gemm_mma_kernel,
                             cudaFuncAttributeMaxDynamicSharedMemorySize,
                             SMEM_GEMM);
        smem_set = true;
    }
    dim3 grid(N_DIM / 128, M / 128);
    gemm_mma_kernel<<<grid, 256, SMEM_GEMM>>>(bias, out);
}

// round 16
// speedup vs baseline: 1.0612x; 1.0612x over previous
#include <cuda_runtime.h>
#include <cuda_fp16.h>
#include <stdint.h>

// ============================================================================
// Problem constants (fixed per reference source)
// ============================================================================
#define K_DIM 4096
#define N_DIM 4096
#define M_MAX 8192
#define HASH_MASK 0xFFFFF        // HASH_SIZE = 2^20
#define P_CONST 56598313LL       // RzLinear.P (prime), hardcoded in reference

// Scratch (device globals; no allocation allowed)
// g_A: fragment-major fp16, [M/16][K/16][32 lanes][4 b32 words]; entry
//      (mt,k16,lane={lq*4+lr}) = m16n8k16 A-fragment.
// g_B: pair-major fp16, uint2 index r*N+n with r = k16*4 + lr:
//      .x = half2(w[k0,n], w[k0+1,n]), .y = half2(w[k0+8,n], w[k0+9,n]),
//      k0 = k16*16 + 2*lr.
__device__ uint32_t g_A[(size_t)M_MAX * K_DIM / 2];
__device__ uint32_t g_B[(size_t)K_DIM * N_DIM / 2];
__device__ int      g_rowmod[K_DIM];              // (k*r3 + r1) % P
__device__ int      g_colmod[N_DIM];              // (n*r2) % P

__device__ __forceinline__ uint32_t pack_h2(float lo, float hi) {
    __half2 h = __floats2half2_rn(lo, hi);
    return *(uint32_t*)&h;
}
__device__ __forceinline__ uint32_t smem_u32(const void* p) {
    uint32_t a;
    asm("{ .reg .u64 t; cvta.to.shared.u64 t, %1; cvt.u32.u64 %0, t; }"
        : "=r"(a) : "l"(p));
    return a;
}
__device__ __forceinline__ void cp_async16(uint32_t dst, const void* src) {
    asm volatile("cp.async.cg.shared.global [%0], [%1], 16;"
                 :: "r"(dst), "l"(src) : "memory");
}
#define CP_COMMIT() asm volatile("cp.async.commit_group;" ::: "memory")
#define CP_WAIT1()  asm volatile("cp.async.wait_group 1;"  ::: "memory")
#define CP_WAIT0()  asm volatile("cp.async.wait_group 0;"  ::: "memory")

// m16n8k16 fp16 MMA, f32 accumulate (generic PTX, sm_80+)
__device__ __forceinline__ void mma_f16(float c[4], uint32_t a0, uint32_t a1,
                                        uint32_t a2, uint32_t a3,
                                        uint32_t b0, uint32_t b1) {
    asm volatile(
        "mma.sync.aligned.m16n8k16.row.col.f32.f16.f16.f32 "
        "{%0,%1,%2,%3}, {%4,%5,%6,%7}, {%8,%9}, {%0,%1,%2,%3};"
        : "+f"(c[0]), "+f"(c[1]), "+f"(c[2]), "+f"(c[3])
        : "r"(a0), "r"(a1), "r"(a2), "r"(a3), "r"(b0), "r"(b1));
}

// ============================================================================
// Kernel 1: hash residue tables (self-detects int64 vs int32 materialization)
// ============================================================================
__global__ void hash_tables_kernel(const void* __restrict__ rn_raw) {
    const long long* rn64 = (const long long*)rn_raw;
    const int*       rn32 = (const int*)rn_raw;
    long long r1, r2, r3;
    if (rn64[0] == P_CONST) { r1 = rn64[1]; r2 = rn64[2]; r3 = rn64[3]; }
    else                    { r1 = rn32[1]; r2 = rn32[2]; r3 = rn32[3]; }
    int i = blockIdx.x * blockDim.x + threadIdx.x;
    if (i < K_DIM) g_rowmod[i] = (int)(((long long)i * r3 + r1) % P_CONST);
    if (i < N_DIM) g_colmod[i] = (int)(((long long)i * r2) % P_CONST);
}

// ============================================================================
// Kernel 2 (fused prep): even blocks convert x -> fp16 fragment-major A;
// odd blocks gather W -> pair-major fp16 B (different bottlenecks overlap).
// ============================================================================
__global__ void prep_kernel(const float* __restrict__ x,
                            const float* __restrict__ hw,
                            int a_total, int g_total) {
    const int half_id = blockIdx.x >> 1;
    if ((blockIdx.x & 1) == 0) {
        // ---- cvt_a: fragment-major permutation ----
        int t = half_id * blockDim.x + threadIdx.x;
        if (t >= a_total) return;
        const int lane = t & 31;
        const int k16  = (t >> 5) & (K_DIM / 16 - 1);
        const int mt   = t >> (5 + 8);            // K/16 = 256 -> 8 bits
        const int lq = lane >> 2, lr = lane & 3;
        const float* xm = x + (size_t)(mt * 16) * K_DIM + k16 * 16;
        const float2 p0 = *(const float2*)(xm + (size_t)lq * K_DIM + 2 * lr);
        const float2 p1 = *(const float2*)(xm + (size_t)(lq + 8) * K_DIM + 2 * lr);
        const float2 p2 = *(const float2*)(xm + (size_t)lq * K_DIM + 2 * lr + 8);
        const float2 p3 = *(const float2*)(xm + (size_t)(lq + 8) * K_DIM + 2 * lr + 8);
        uint4 o;
        o.x = pack_h2(p0.x, p0.y);
        o.y = pack_h2(p1.x, p1.y);
        o.z = pack_h2(p2.x, p2.y);
        o.w = pack_h2(p3.x, p3.y);
        ((uint4*)g_A)[t] = o;
    } else {
        // ---- gather: W -> pair-major fp16 ----
        const int P = (int)P_CONST;
        int t = half_id * blockDim.x + threadIdx.x;
        if (t >= g_total) return;
        const int n  = t & (N_DIM - 1);
        const int r  = t >> 12;                     // k16*4 + lr
        const int lr = r & 3;
        const int k0 = (r >> 2) * 16 + 2 * lr;

        const int rm0 = g_rowmod[k0];
        const int rm1 = g_rowmod[k0 + 1];
        const int rm2 = g_rowmod[k0 + 8];
        const int rm3 = g_rowmod[k0 + 9];
        const int c   = g_colmod[n];

        int s0 = rm0 + c; if (s0 >= P) s0 -= P;
        int s1 = rm1 + c; if (s1 >= P) s1 -= P;
        int s2 = rm2 + c; if (s2 >= P) s2 -= P;
        int s3 = rm3 + c; if (s3 >= P) s3 -= P;

        const float w0 = __ldg(hw + (s0 & HASH_MASK));
        const float w1 = __ldg(hw + (s1 & HASH_MASK));
        const float w2 = __ldg(hw + (s2 & HASH_MASK));
        const float w3 = __ldg(hw + (s3 & HASH_MASK));

        uint2 o;
        o.x = pack_h2(w0, w1);
        o.y = pack_h2(w2, w3);
        ((uint2*)g_B)[t] = o;
    }
}

// ============================================================================
// Kernel 3: fp16 tensor-core GEMM via mma.sync m16n8k16
//   CTA tile 128x128, STAGE = 64 k (4 k16-steps), 256 thr (8 warps 2x4 ->
//   warp tile 64x32), 3-stage cp.async pipeline, ONE barrier per 64 k,
//   2 CTAs per SM (barrier decoupling across independent CTAs).
//   Prefetch placement (R16): issued AFTER the first 16-MMA burst —
//   the first burst starts immediately off the barrier (R15's startup
//   delay avoided) while the async group still gets 3 remaining bursts
//   plus the next stage to land (more slack than R14's end-of-stage
//   placement). Slot safety: (st+2)%3 = (kt-1)%3 was last read in iter
//   kt-1, before the barrier above.
//   A fragments: 1x LDS.128 (fragment-major, conflict-free).
//   B fragments: 1x LDS.64 (pair-major, SB_W=264 ≡ 8 mod 32 words).
// ============================================================================
#define SB_W 264
#define A_STAGE_B (8 * 4 * 32 * 16)                // 16384 (8 mtiles x 4 ks)
#define B_STAGE_B (16 * SB_W * 4)                  // 16896 (16 rows)
#define STAGE_B   (A_STAGE_B + B_STAGE_B)          // 33280
#define NSTAGE 3
#define SMEM_GEMM (NSTAGE * STAGE_B)               // 99840 (x2 CTAs = 199680)
#define NK64      (K_DIM / 64)                     // 64 stages of work

__device__ __forceinline__ void load_stage(uint32_t sbase, int stage,
                                           int m0, int n0, int kt, int tid) {
    const uint32_t a_s = sbase + stage * STAGE_B;
    const uint32_t b_s = a_s + A_STAGE_B;
    // A: 32 fragment-chunks of 512B (i = mtile 0..7, j = ks 0..3);
    //    1024 x 16B transfers, 4 per thread; gmem chunk contiguous.
    #pragma unroll
    for (int p = 0; p < 4; p++) {
        const int u     = tid + p * 256;
        const int chunk = u >> 5;            // 0..31
        const int lane  = u & 31;
        const int i = chunk >> 2;            // mtile within CTA
        const int j = chunk & 3;             // ks
        const uint32_t* src = g_A +
            (((size_t)(m0 / 16 + i) * (K_DIM / 16) + (kt * 4 + j)) * 32
             + lane) * 4;
        cp_async16(a_s + u * 16, src);
    }
    // B: 16 rows x 256 words (64 x 16B chunks per row); 4 per thread.
    #pragma unroll
    for (int p = 0; p < 4; p++) {
        const int u = tid + p * 256;
        const int r = u >> 6;                // 0..15
        const int c = u & 63;
        const uint32_t* src =
            g_B + ((size_t)(kt * 16 + r) * N_DIM + n0) * 2 + c * 4;
        cp_async16(b_s + r * (SB_W * 4) + c * 16, src);
    }
}

__global__ __launch_bounds__(256, 2)
void gemm_mma_kernel(const float* __restrict__ bias, float* __restrict__ C) {
    extern __shared__ char smem[];
    const uint32_t sbase = smem_u32(smem);
    const int tid  = threadIdx.x;
    const int wid  = tid >> 5;
    const int lane = tid & 31;
    const int lq = lane >> 2;     // 0..7
    const int lr = lane & 3;      // 0..3
    const int wm = wid & 1;       // 2 m-halves of 64
    const int wn = wid >> 1;      // 4 n-slices of 32

    const int m_blk = blockIdx.y * 128;
    const int n_blk = blockIdx.x * 128;

    float acc[4][4][4];
    #pragma unroll
    for (int i = 0; i < 4; i++)
        #pragma unroll
        for (int j = 0; j < 4; j++)
            #pragma unroll
            for (int r = 0; r < 4; r++) acc[i][j][r] = 0.0f;

    load_stage(sbase, 0, m_blk, n_blk, 0, tid); CP_COMMIT();
    load_stage(sbase, 1, m_blk, n_blk, 1, tid); CP_COMMIT();

    int st = 0;
    for (int kt = 0; kt < NK64; kt++) {
        CP_WAIT1();
        __syncthreads();    // single barrier per 64 k

        const uint32_t* As = (const uint32_t*)(smem + st * STAGE_B);
        const uint32_t* Bs = (const uint32_t*)(smem + st * STAGE_B + A_STAGE_B);
        const uint32_t* a_base = As + (wm * 16) * 128 + lane * 4;
        const uint32_t* b_base = Bs + (wn * 32 + lq) * 2;

        // ---- ks = 0: starts immediately off the barrier ----
        {
            uint4 a[4];
            #pragma unroll
            for (int im = 0; im < 4; im++)
                a[im] = *(const uint4*)(a_base + (im * 4) * 128);
            uint2 b[4];
            #pragma unroll
            for (int jn = 0; jn < 4; jn++)
                b[jn] = *(const uint2*)(b_base + lr * SB_W + jn * 16);
            #pragma unroll
            for (int im = 0; im < 4; im++)
                #pragma unroll
                for (int jn = 0; jn < 4; jn++)
                    mma_f16(acc[im][jn], a[im].x, a[im].y, a[im].z, a[im].w,
                            b[jn].x, b[jn].y);
        }

        // ---- prefetch kt+2 under the remaining 3 bursts ----
        if (kt + 2 < NK64) {
            int ws = st + 2; if (ws >= NSTAGE) ws -= NSTAGE;
            load_stage(sbase, ws, m_blk, n_blk, kt + 2, tid);
        }
        CP_COMMIT();   // keep group count in lockstep even when empty

        // ---- ks = 1..3 ----
        #pragma unroll
        for (int ks = 1; ks < 4; ks++) {
            uint4 a[4];
            #pragma unroll
            for (int im = 0; im < 4; im++)
                a[im] = *(const uint4*)(a_base + (im * 4 + ks) * 128);
            uint2 b[4];
            #pragma unroll
            for (int jn = 0; jn < 4; jn++)
                b[jn] = *(const uint2*)
                    (b_base + (ks * 4 + lr) * SB_W + jn * 16);
            #pragma unroll
            for (int im = 0; im < 4; im++)
                #pragma unroll
                for (int jn = 0; jn < 4; jn++)
                    mma_f16(acc[im][jn], a[im].x, a[im].y, a[im].z, a[im].w,
                            b[jn].x, b[jn].y);
        }

        st = (st == NSTAGE - 1) ? 0 : st + 1;
    }
    CP_WAIT0();

    // epilogue: bias + direct stores
    #pragma unroll
    for (int jn = 0; jn < 4; jn++) {
        const int c0 = n_blk + wn * 32 + jn * 8 + 2 * lr;
        const float bx = __ldg(bias + c0);
        const float by = __ldg(bias + c0 + 1);
        #pragma unroll
        for (int im = 0; im < 4; im++) {
            const int r0 = m_blk + wm * 64 + im * 16 + lq;
            float2 v0, v1;
            v0.x = acc[im][jn][0] + bx; v0.y = acc[im][jn][1] + by;
            v1.x = acc[im][jn][2] + bx; v1.y = acc[im][jn][3] + by;
            *(float2*)(C + (size_t)r0 * N_DIM + c0)       = v0;
            *(float2*)(C + (size_t)(r0 + 8) * N_DIM + c0) = v1;
        }
    }
}

// ============================================================================
// Host launch. Inputs routed by element count (immune to metadata ordering):
//   <=8 elems -> random_numbers; 2^20 -> hashed_weight; 4096 -> bias;
//   largest -> x. Output f32 [M, N_DIM].
// ============================================================================
extern "C" void kernel_launch(void* const* d_in, const int* in_sizes, int n_in,
                              void* d_out, int out_size) {
    const float* x = nullptr; const float* hw = nullptr;
    const void* rn = nullptr; const float* bias = nullptr;
    long long max_sz = -1; int max_i = 0;
    for (int i = 0; i < n_in; i++)
        if ((long long)in_sizes[i] > max_sz) { max_sz = in_sizes[i]; max_i = i; }
    x = (const float*)d_in[max_i];
    for (int i = 0; i < n_in; i++) {
        if (i == max_i) continue;
        if (in_sizes[i] <= 8)              rn   = d_in[i];
        else if (in_sizes[i] == (1 << 20)) hw   = (const float*)d_in[i];
        else if (in_sizes[i] == N_DIM)     bias = (const float*)d_in[i];
    }
    float* out = (float*)d_out;
    const int M = (int)(max_sz / K_DIM);   // 8192

    hash_tables_kernel<<<(K_DIM + 255) / 256, 256>>>(rn);

    const int a_total = (M / 16) * (K_DIM / 16) * 32;
    const int g_total = (K_DIM / 4) * N_DIM;
    const int a_blocks = (a_total + 255) / 256;
    const int g_blocks = (g_total + 255) / 256;
    const int mx_blocks = (a_blocks > g_blocks ? a_blocks : g_blocks);
    prep_kernel<<<2 * mx_blocks, 256>>>(x, hw, a_total, g_total);

    static bool smem_set = false;
    if (!smem_set) {
        cudaFuncSetAttribute(gemm_mma_kernel,
                             cudaFuncAttributeMaxDynamicSharedMemorySize,
                             SMEM_GEMM);
        smem_set = true;
    }
    dim3 grid(N_DIM / 128, M / 128);
    gemm_mma_kernel<<<grid, 256, SMEM_GEMM>>>(bias, out);
}

// round 17
// speedup vs baseline: 1.0749x; 1.0129x over previous
#include <cuda_runtime.h>
#include <cuda_fp16.h>
#include <stdint.h>

// ============================================================================
// Problem constants (fixed per reference source)
// ============================================================================
#define K_DIM 4096
#define N_DIM 4096
#define M_MAX 8192
#define HASH_MASK 0xFFFFF        // HASH_SIZE = 2^20
#define P_CONST 56598313LL       // RzLinear.P (prime), hardcoded in reference

// Scratch (device globals; no allocation allowed)
// g_A: fragment-major fp16, [M/16][K/16][32 lanes][4 b32 words]; entry
//      (mt,k16,lane={lq*4+lr}) = m16n8k16 A-fragment.
// g_B: pair-major fp16, uint2 index r*N+n with r = k16*4 + lr:
//      .x = half2(w[k0,n], w[k0+1,n]), .y = half2(w[k0+8,n], w[k0+9,n]),
//      k0 = k16*16 + 2*lr.
__device__ uint32_t g_A[(size_t)M_MAX * K_DIM / 2];
__device__ uint32_t g_B[(size_t)K_DIM * N_DIM / 2];
__device__ int      g_rowmod[K_DIM];              // (k*r3 + r1) % P
__device__ int      g_colmod[N_DIM];              // (n*r2) % P

__device__ __forceinline__ uint32_t pack_h2(float lo, float hi) {
    __half2 h = __floats2half2_rn(lo, hi);
    return *(uint32_t*)&h;
}
__device__ __forceinline__ uint32_t smem_u32(const void* p) {
    uint32_t a;
    asm("{ .reg .u64 t; cvta.to.shared.u64 t, %1; cvt.u32.u64 %0, t; }"
        : "=r"(a) : "l"(p));
    return a;
}
__device__ __forceinline__ void cp_async16(uint32_t dst, const void* src) {
    asm volatile("cp.async.cg.shared.global [%0], [%1], 16;"
                 :: "r"(dst), "l"(src) : "memory");
}

// ---- mbarrier primitives (generic PTX, sm_90-class syntax, ok for 103) ----
#define MBAR_INIT(a, c) \
    asm volatile("mbarrier.init.shared.b64 [%0], %1;" \
        :: "r"((uint32_t)(a)), "r"((uint32_t)(c)) : "memory")
#define MBAR_ARRIVE(a) \
    asm volatile("mbarrier.arrive.shared.b64 _, [%0];" \
        :: "r"((uint32_t)(a)) : "memory")
// arrive-on full barrier when all prior cp.async of this thread complete
#define CP_MBAR_ARRIVE_NOINC(a) \
    asm volatile("cp.async.mbarrier.arrive.noinc.shared.b64 [%0];" \
        :: "r"((uint32_t)(a)) : "memory")

#define MBAR_WAIT_PARITY_ACQ(mbar_addr, parity) do {                          \
    uint32_t _mbar = (uint32_t)(mbar_addr);                                   \
    uint32_t _par  = (uint32_t)(parity);                                      \
    asm volatile(                                                             \
        "{\n\t.reg .pred P1;\n\t"                                             \
        "WAIT_LOOP_%=:\n\t"                                                   \
        "mbarrier.try_wait.parity.acquire.cta.shared::cta.b64 P1, [%0], %1, 0x989680;\n\t" \
        "@P1 bra.uni WAIT_DONE_%=;\n\t"                                       \
        "bra.uni WAIT_LOOP_%=;\n\t"                                           \
        "WAIT_DONE_%=:\n\t}"                                                  \
        :: "r"(_mbar), "r"(_par) : "memory");                                 \
} while (0)

#define MBAR_WAIT_PARITY_RELAXED(mbar_addr, parity) do {                      \
    uint32_t _mbar = (uint32_t)(mbar_addr);                                   \
    uint32_t _par  = (uint32_t)(parity);                                      \
    asm volatile(                                                             \
        "{\n\t.reg .pred P1;\n\t"                                             \
        "WAIT_LOOP_%=:\n\t"                                                   \
        "mbarrier.try_wait.parity.relaxed.cta.shared::cta.b64 P1, [%0], %1, 0x989680;\n\t" \
        "@P1 bra.uni WAIT_DONE_%=;\n\t"                                       \
        "bra.uni WAIT_LOOP_%=;\n\t"                                           \
        "WAIT_DONE_%=:\n\t}"                                                  \
        :: "r"(_mbar), "r"(_par) : "memory");                                 \
} while (0)

// m16n8k16 fp16 MMA, f32 accumulate (generic PTX, sm_80+)
__device__ __forceinline__ void mma_f16(float c[4], uint32_t a0, uint32_t a1,
                                        uint32_t a2, uint32_t a3,
                                        uint32_t b0, uint32_t b1) {
    asm volatile(
        "mma.sync.aligned.m16n8k16.row.col.f32.f16.f16.f32 "
        "{%0,%1,%2,%3}, {%4,%5,%6,%7}, {%8,%9}, {%0,%1,%2,%3};"
        : "+f"(c[0]), "+f"(c[1]), "+f"(c[2]), "+f"(c[3])
        : "r"(a0), "r"(a1), "r"(a2), "r"(a3), "r"(b0), "r"(b1));
}

// ============================================================================
// Kernel 1: hash residue tables (self-detects int64 vs int32 materialization)
// ============================================================================
__global__ void hash_tables_kernel(const void* __restrict__ rn_raw) {
    const long long* rn64 = (const long long*)rn_raw;
    const int*       rn32 = (const int*)rn_raw;
    long long r1, r2, r3;
    if (rn64[0] == P_CONST) { r1 = rn64[1]; r2 = rn64[2]; r3 = rn64[3]; }
    else                    { r1 = rn32[1]; r2 = rn32[2]; r3 = rn32[3]; }
    int i = blockIdx.x * blockDim.x + threadIdx.x;
    if (i < K_DIM) g_rowmod[i] = (int)(((long long)i * r3 + r1) % P_CONST);
    if (i < N_DIM) g_colmod[i] = (int)(((long long)i * r2) % P_CONST);
}

// ============================================================================
// Kernel 2 (fused prep): even blocks convert x -> fp16 fragment-major A;
// odd blocks gather W -> pair-major fp16 B (different bottlenecks overlap).
// ============================================================================
__global__ void prep_kernel(const float* __restrict__ x,
                            const float* __restrict__ hw,
                            int a_total, int g_total) {
    const int half_id = blockIdx.x >> 1;
    if ((blockIdx.x & 1) == 0) {
        // ---- cvt_a: fragment-major permutation ----
        int t = half_id * blockDim.x + threadIdx.x;
        if (t >= a_total) return;
        const int lane = t & 31;
        const int k16  = (t >> 5) & (K_DIM / 16 - 1);
        const int mt   = t >> (5 + 8);            // K/16 = 256 -> 8 bits
        const int lq = lane >> 2, lr = lane & 3;
        const float* xm = x + (size_t)(mt * 16) * K_DIM + k16 * 16;
        const float2 p0 = *(const float2*)(xm + (size_t)lq * K_DIM + 2 * lr);
        const float2 p1 = *(const float2*)(xm + (size_t)(lq + 8) * K_DIM + 2 * lr);
        const float2 p2 = *(const float2*)(xm + (size_t)lq * K_DIM + 2 * lr + 8);
        const float2 p3 = *(const float2*)(xm + (size_t)(lq + 8) * K_DIM + 2 * lr + 8);
        uint4 o;
        o.x = pack_h2(p0.x, p0.y);
        o.y = pack_h2(p1.x, p1.y);
        o.z = pack_h2(p2.x, p2.y);
        o.w = pack_h2(p3.x, p3.y);
        ((uint4*)g_A)[t] = o;
    } else {
        // ---- gather: W -> pair-major fp16 ----
        const int P = (int)P_CONST;
        int t = half_id * blockDim.x + threadIdx.x;
        if (t >= g_total) return;
        const int n  = t & (N_DIM - 1);
        const int r  = t >> 12;                     // k16*4 + lr
        const int lr = r & 3;
        const int k0 = (r >> 2) * 16 + 2 * lr;

        const int rm0 = g_rowmod[k0];
        const int rm1 = g_rowmod[k0 + 1];
        const int rm2 = g_rowmod[k0 + 8];
        const int rm3 = g_rowmod[k0 + 9];
        const int c   = g_colmod[n];

        int s0 = rm0 + c; if (s0 >= P) s0 -= P;
        int s1 = rm1 + c; if (s1 >= P) s1 -= P;
        int s2 = rm2 + c; if (s2 >= P) s2 -= P;
        int s3 = rm3 + c; if (s3 >= P) s3 -= P;

        const float w0 = __ldg(hw + (s0 & HASH_MASK));
        const float w1 = __ldg(hw + (s1 & HASH_MASK));
        const float w2 = __ldg(hw + (s2 & HASH_MASK));
        const float w3 = __ldg(hw + (s3 & HASH_MASK));

        uint2 o;
        o.x = pack_h2(w0, w1);
        o.y = pack_h2(w2, w3);
        ((uint2*)g_B)[t] = o;
    }
}

// ============================================================================
// Kernel 3: fp16 tensor-core GEMM via mma.sync m16n8k16
//   CTA tile 128x128, STAGE = 64 k (4 k16-steps), 256 thr (8 warps 2x4 ->
//   warp tile 64x32), 2 CTAs per SM, 3-slot mbarrier producer/consumer ring
//   instead of __syncthreads + cp.async.wait_group:
//     full[s]  (256): cp.async.mbarrier.arrive.noinc per thread per fill —
//                     flips when the slot's DATA is resident, independent of
//                     other warps' compute progress.
//     empty[s] (256): each thread arrives after its last read of the slot;
//                     refill waits it (relaxed: post-wait writes are
//                     async-proxy cp.async).
//   Warps proceed with ~1 stage of skew tolerance (was 0 with bar.sync).
//   Prefetch placement kept from R16: issued after the first 16-MMA burst.
//   A fragments: 1x LDS.128 (fragment-major, conflict-free).
//   B fragments: 1x LDS.64 (pair-major, SB_W=264 ≡ 8 mod 32 words).
// ============================================================================
#define SB_W 264
#define A_STAGE_B (8 * 4 * 32 * 16)                // 16384 (8 mtiles x 4 ks)
#define B_STAGE_B (16 * SB_W * 4)                  // 16896 (16 rows)
#define STAGE_B   (A_STAGE_B + B_STAGE_B)          // 33280
#define NSTAGE 3
#define SMEM_DATA_OFF 128                          // barriers live in [0,48)
#define SMEM_GEMM (SMEM_DATA_OFF + NSTAGE * STAGE_B)   // 99968 (x2 = 199936)
#define NK64      (K_DIM / 64)                     // 64 stages of work
#define MB_FULL(sb, s)  ((sb) + (s) * 8)
#define MB_EMPTY(sb, s) ((sb) + 24 + (s) * 8)

__device__ __forceinline__ void load_stage(uint32_t sbase, int slot,
                                           int m0, int n0, int kt, int tid) {
    const uint32_t a_s = sbase + SMEM_DATA_OFF + slot * STAGE_B;
    const uint32_t b_s = a_s + A_STAGE_B;
    // A: 32 fragment-chunks of 512B (i = mtile 0..7, j = ks 0..3);
    //    1024 x 16B transfers, 4 per thread; gmem chunk contiguous.
    #pragma unroll
    for (int p = 0; p < 4; p++) {
        const int u     = tid + p * 256;
        const int chunk = u >> 5;            // 0..31
        const int lane  = u & 31;
        const int i = chunk >> 2;            // mtile within CTA
        const int j = chunk & 3;             // ks
        const uint32_t* src = g_A +
            (((size_t)(m0 / 16 + i) * (K_DIM / 16) + (kt * 4 + j)) * 32
             + lane) * 4;
        cp_async16(a_s + u * 16, src);
    }
    // B: 16 rows x 256 words (64 x 16B chunks per row); 4 per thread.
    #pragma unroll
    for (int p = 0; p < 4; p++) {
        const int u = tid + p * 256;
        const int r = u >> 6;                // 0..15
        const int c = u & 63;
        const uint32_t* src =
            g_B + ((size_t)(kt * 16 + r) * N_DIM + n0) * 2 + c * 4;
        cp_async16(b_s + r * (SB_W * 4) + c * 16, src);
    }
}

__global__ __launch_bounds__(256, 2)
void gemm_mma_kernel(const float* __restrict__ bias, float* __restrict__ C) {
    extern __shared__ char smem[];
    const uint32_t sbase = smem_u32(smem);
    const int tid  = threadIdx.x;
    const int wid  = tid >> 5;
    const int lane = tid & 31;
    const int lq = lane >> 2;     // 0..7
    const int lr = lane & 3;      // 0..3
    const int wm = wid & 1;       // 2 m-halves of 64
    const int wn = wid >> 1;      // 4 n-slices of 32

    const int m_blk = blockIdx.y * 128;
    const int n_blk = blockIdx.x * 128;

    // init ring barriers (full/empty x 3, 256 arrivals each)
    if (tid == 0) {
        #pragma unroll
        for (int s = 0; s < NSTAGE; s++) {
            MBAR_INIT(MB_FULL(sbase, s), 256);
            MBAR_INIT(MB_EMPTY(sbase, s), 256);
        }
    }
    __syncthreads();

    float acc[4][4][4];
    #pragma unroll
    for (int i = 0; i < 4; i++)
        #pragma unroll
        for (int j = 0; j < 4; j++)
            #pragma unroll
            for (int r = 0; r < 4; r++) acc[i][j][r] = 0.0f;

    // prologue: fill slots 0 and 1 (fresh -> no empty wait needed)
    load_stage(sbase, 0, m_blk, n_blk, 0, tid);
    CP_MBAR_ARRIVE_NOINC(MB_FULL(sbase, 0));
    load_stage(sbase, 1, m_blk, n_blk, 1, tid);
    CP_MBAR_ARRIVE_NOINC(MB_FULL(sbase, 1));

    // cursors (scalar ints -> no local-mem arrays)
    int cst = 0, cph = 0;        // consumer: slot / phase
    int pst = 2, pph = 1;        // producer: next fill slot / phase (flip trick)

    for (int kt = 0; kt < NK64; kt++) {
        // wait for this stage's DATA (not other warps' compute)
        MBAR_WAIT_PARITY_ACQ(MB_FULL(sbase, cst), cph);

        const uint32_t* As =
            (const uint32_t*)(smem + SMEM_DATA_OFF + cst * STAGE_B);
        const uint32_t* Bs =
            (const uint32_t*)(smem + SMEM_DATA_OFF + cst * STAGE_B + A_STAGE_B);
        const uint32_t* a_base = As + (wm * 16) * 128 + lane * 4;
        const uint32_t* b_base = Bs + (wn * 32 + lq) * 2;

        // ---- ks = 0: starts immediately off the full-wait ----
        {
            uint4 a[4];
            #pragma unroll
            for (int im = 0; im < 4; im++)
                a[im] = *(const uint4*)(a_base + (im * 4) * 128);
            uint2 b[4];
            #pragma unroll
            for (int jn = 0; jn < 4; jn++)
                b[jn] = *(const uint2*)(b_base + lr * SB_W + jn * 16);
            #pragma unroll
            for (int im = 0; im < 4; im++)
                #pragma unroll
                for (int jn = 0; jn < 4; jn++)
                    mma_f16(acc[im][jn], a[im].x, a[im].y, a[im].z, a[im].w,
                            b[jn].x, b[jn].y);
        }

        // ---- refill slot pst for stage kt+2 under the remaining bursts ----
        if (kt + 2 < NK64) {
            MBAR_WAIT_PARITY_RELAXED(MB_EMPTY(sbase, pst), pph);
            load_stage(sbase, pst, m_blk, n_blk, kt + 2, tid);
            CP_MBAR_ARRIVE_NOINC(MB_FULL(sbase, pst));
            if (pst == NSTAGE - 1) { pst = 0; pph ^= 1; } else pst++;
        }

        // ---- ks = 1..3 ----
        #pragma unroll
        for (int ks = 1; ks < 4; ks++) {
            uint4 a[4];
            #pragma unroll
            for (int im = 0; im < 4; im++)
                a[im] = *(const uint4*)(a_base + (im * 4 + ks) * 128);
            uint2 b[4];
            #pragma unroll
            for (int jn = 0; jn < 4; jn++)
                b[jn] = *(const uint2*)
                    (b_base + (ks * 4 + lr) * SB_W + jn * 16);
            #pragma unroll
            for (int im = 0; im < 4; im++)
                #pragma unroll
                for (int jn = 0; jn < 4; jn++)
                    mma_f16(acc[im][jn], a[im].x, a[im].y, a[im].z, a[im].w,
                            b[jn].x, b[jn].y);
        }

        // done reading slot cst
        MBAR_ARRIVE(MB_EMPTY(sbase, cst));
        if (cst == NSTAGE - 1) { cst = 0; cph ^= 1; } else cst++;
    }

    // epilogue: bias + direct stores
    #pragma unroll
    for (int jn = 0; jn < 4; jn++) {
        const int c0 = n_blk + wn * 32 + jn * 8 + 2 * lr;
        const float bx = __ldg(bias + c0);
        const float by = __ldg(bias + c0 + 1);
        #pragma unroll
        for (int im = 0; im < 4; im++) {
            const int r0 = m_blk + wm * 64 + im * 16 + lq;
            float2 v0, v1;
            v0.x = acc[im][jn][0] + bx; v0.y = acc[im][jn][1] + by;
            v1.x = acc[im][jn][2] + bx; v1.y = acc[im][jn][3] + by;
            *(float2*)(C + (size_t)r0 * N_DIM + c0)       = v0;
            *(float2*)(C + (size_t)(r0 + 8) * N_DIM + c0) = v1;
        }
    }
}

// ============================================================================
// Host launch. Inputs routed by element count (immune to metadata ordering):
//   <=8 elems -> random_numbers; 2^20 -> hashed_weight; 4096 -> bias;
//   largest -> x. Output f32 [M, N_DIM].
// ============================================================================
extern "C" void kernel_launch(void* const* d_in, const int* in_sizes, int n_in,
                              void* d_out, int out_size) {
    const float* x = nullptr; const float* hw = nullptr;
    const void* rn = nullptr; const float* bias = nullptr;
    long long max_sz = -1; int max_i = 0;
    for (int i = 0; i < n_in; i++)
        if ((long long)in_sizes[i] > max_sz) { max_sz = in_sizes[i]; max_i = i; }
    x = (const float*)d_in[max_i];
    for (int i = 0; i < n_in; i++) {
        if (i == max_i) continue;
        if (in_sizes[i] <= 8)              rn   = d_in[i];
        else if (in_sizes[i] == (1 << 20)) hw   = (const float*)d_in[i];
        else if (in_sizes[i] == N_DIM)     bias = (const float*)d_in[i];
    }
    float* out = (float*)d_out;
    const int M = (int)(max_sz / K_DIM);   // 8192

    hash_tables_kernel<<<(K_DIM + 255) / 256, 256>>>(rn);

    const int a_total = (M / 16) * (K_DIM / 16) * 32;
    const int g_total = (K_DIM / 4) * N_DIM;
    const int a_blocks = (a_total + 255) / 256;
    const int g_blocks = (g_total + 255) / 256;
    const int mx_blocks = (a_blocks > g_blocks ? a_blocks : g_blocks);
    prep_kernel<<<2 * mx_blocks, 256>>>(x, hw, a_total, g_total);

    static bool smem_set = false;
    if (!smem_set) {
        cudaFuncSetAttribute(gemm_mma_kernel,
                             cudaFuncAttributeMaxDynamicSharedMemorySize,
                             SMEM_GEMM);
        smem_set = true;
    }
    dim3 grid(N_DIM / 128, M / 128);
    gemm_mma_kernel<<<grid, 256, SMEM_GEMM>>>(bias, out);
}